// round 10
// baseline (speedup 1.0000x reference)
#include <cuda_runtime.h>
#include <cuda_fp16.h>
#include <cstdint>

#define NB    16
#define CIN   512
#define COUT  512
#define STY   512
#define HW    4096
#define EPSV  1e-8f

#define XM_ELEMS (NB * 32 * HW * 16)
#define NTILES_TOTAL 1024
#define NCTA 148

// ---------------- device scratch ----------------
__device__ float g_s[NB * CIN];
__device__ float g_demod[NB * COUT];
__device__ float g_wsq[COUT * CIN];
__device__ __align__(16) __half g_xm[XM_ELEMS];          // x*s fp16, [n][c16][p][16]
__device__ __align__(16) __half g_wB[32 * 4 * 9 * 128 * 16]; // [c16][cotile][tap][co128][16ci]
__device__ __align__(16) __half g_zero[1024];            // 2 KB zeros

// ---------------- PTX helpers ----------------
__device__ __forceinline__ uint32_t smem_u32(const void* p) {
    uint32_t a;
    asm("{ .reg .u64 t; cvta.to.shared.u64 t, %1; cvt.u32.u64 %0, t; }" : "=r"(a) : "l"(p));
    return a;
}
#define MBAR_INIT(mb, c) asm volatile("mbarrier.init.shared.b64 [%0], %1;" :: "r"((uint32_t)(mb)), "r"((uint32_t)(c)) : "memory")
#define MBAR_ARRIVE(mb)  asm volatile("mbarrier.arrive.shared.b64 _, [%0];" :: "r"((uint32_t)(mb)) : "memory")
#define MBAR_EXPECT(mb, n) asm volatile("mbarrier.arrive.expect_tx.shared.b64 _, [%0], %1;" :: "r"((uint32_t)(mb)), "r"((uint32_t)(n)) : "memory")
#define FENCE_ASYNC()    asm volatile("fence.proxy.async.shared::cta;" ::: "memory")

#define MBAR_WAIT(mb, ph) do {                                                   \
    uint32_t _mb = (uint32_t)(mb); uint32_t _ph = (uint32_t)(ph); uint32_t _dn;  \
    asm volatile("{ .reg .pred p; mbarrier.try_wait.parity.acquire.cta.shared::cta.b64 p, [%1], %2; selp.b32 %0, 1, 0, p; }" \
        : "=r"(_dn) : "r"(_mb), "r"(_ph) : "memory");                            \
    if (!_dn) {                                                                  \
        asm volatile("{ .reg .pred P1;\n"                                        \
            "WL_%=: mbarrier.try_wait.parity.acquire.cta.shared::cta.b64 P1, [%0], %1, 0x989680;\n" \
            "@P1 bra.uni WD_%=;\n bra.uni WL_%=;\n WD_%=: }"                     \
            :: "r"(_mb), "r"(_ph) : "memory");                                   \
    }                                                                            \
} while (0)

#define BULK(dst, src, sz, mb) \
    asm volatile("cp.async.bulk.shared::cta.global.mbarrier::complete_tx::bytes [%0], [%1], %2, [%3];" \
        :: "r"((uint32_t)(dst)), "l"(src), "r"((uint32_t)(sz)), "r"((uint32_t)(mb)) : "memory")

#define LDSM4(r, a) \
    asm volatile("ldmatrix.sync.aligned.m8n8.x4.shared.b16 {%0,%1,%2,%3}, [%4];" \
        : "=r"((r)[0]), "=r"((r)[1]), "=r"((r)[2]), "=r"((r)[3]) : "r"(a))

__device__ __forceinline__ void mma_f16(float* c, const uint32_t* a, const uint32_t* b) {
    asm volatile("mma.sync.aligned.m16n8k16.row.col.f32.f16.f16.f32 "
        "{%0,%1,%2,%3}, {%4,%5,%6,%7}, {%8,%9}, {%0,%1,%2,%3};"
        : "+f"(c[0]), "+f"(c[1]), "+f"(c[2]), "+f"(c[3])
        : "r"(a[0]), "r"(a[1]), "r"(a[2]), "r"(a[3]), "r"(b[0]), "r"(b[1]));
}

// ---------------- prep kernels ----------------
__global__ void k_style(const float* __restrict__ style,
                        const float* __restrict__ style_w,
                        const float* __restrict__ style_b) {
    int n = blockIdx.x, ci = threadIdx.x;
    const float* srow = style + n * STY;
    const float* wrow = style_w + ci * STY;
    float acc = 0.f;
    #pragma unroll 8
    for (int j = 0; j < STY; j++) acc += srow[j] * wrow[j];
    g_s[n * CIN + ci] = acc + style_b[ci];
}

__global__ void k_wprep(const float* __restrict__ weight) {
    int id = blockIdx.x * 256 + threadIdx.x;
    int ci = id & 511, co = id >> 9;
    const float* wp = weight + (size_t)(co * CIN + ci) * 9;
    int c16 = ci >> 4, cil = ci & 15;
    int cotile = co >> 7, col = co & 127;
    float s = 0.f;
    #pragma unroll
    for (int tap = 0; tap < 9; tap++) {
        float v = wp[tap];
        s += v * v;
        g_wB[(((size_t)(c16 * 4 + cotile) * 9 + tap) * 128 + col) * 16 + cil] =
            __float2half_rn(v);
    }
    g_wsq[co * CIN + ci] = s;
}

__global__ void k_demod() {
    int co = blockIdx.x, n = blockIdx.y;
    __shared__ float red[128];
    float acc = 0.f;
    for (int ci = threadIdx.x; ci < CIN; ci += 128) {
        float s = g_s[n * CIN + ci];
        acc += g_wsq[co * CIN + ci] * s * s;
    }
    red[threadIdx.x] = acc;
    __syncthreads();
    for (int st = 64; st > 0; st >>= 1) {
        if (threadIdx.x < st) red[threadIdx.x] += red[threadIdx.x + st];
        __syncthreads();
    }
    if (threadIdx.x == 0) g_demod[n * COUT + co] = rsqrtf(red[0] + EPSV);
}

__global__ void k_xmod(const float* __restrict__ x) {
    int b   = blockIdx.x;
    int n   = b >> 9;
    int c16 = (b >> 4) & 31;
    int pb  = b & 15;
    int p   = pb * 256 + threadIdx.x;
    const float* sp = g_s + n * CIN + c16 * 16;
    const float* xp = x + (size_t)(n * CIN + c16 * 16) * HW + p;
    uint32_t hi[8];
    #pragma unroll
    for (int j = 0; j < 8; j++) {
        float v0 = xp[(size_t)(2 * j) * HW]     * sp[2 * j];
        float v1 = xp[(size_t)(2 * j + 1) * HW] * sp[2 * j + 1];
        __half2 hp = __halves2half2(__float2half_rn(v0), __float2half_rn(v1));
        hi[j] = *reinterpret_cast<uint32_t*>(&hp);
    }
    size_t ob = ((size_t)(n * 32 + c16) * HW + p) * 16;
    uint4* oh = reinterpret_cast<uint4*>(g_xm + ob);
    oh[0] = make_uint4(hi[0], hi[1], hi[2], hi[3]);
    oh[1] = make_uint4(hi[4], hi[5], hi[6], hi[7]);
}

// ---------------- main HMMA kernel (persistent, A+B double-buffered frags) ----
#define A_BYTES   12672
#define B_BYTES   36864
#define SSTRIDE   (A_BYTES + B_BYTES)    // 49536
#define SM_DATA   1024
#define SM_EPI    (SM_DATA + 2 * SSTRIDE)        // 100096
#define SMEM_TOTAL (SM_EPI + 8 * 2048)           // 116480
#define EXPECT_B  (6 * 2048 + B_BYTES)           // 49152

__device__ __forceinline__ void issue_stage(uint32_t sb, int ls, int bx) {
    int tord = ls >> 5, c16 = ls & 31;
    int tile = bx + NCTA * tord;
    int n = tile >> 6, rem = tile & 63;
    int h0 = (rem >> 2) * 4;
    int cotile = rem & 3;
    int slot = ls & 1;
    uint32_t sa = sb + SM_DATA + slot * SSTRIDE;
    uint32_t mb = sb + slot * 8;
    MBAR_EXPECT(mb, EXPECT_B);
    const __half* xbase = g_xm + ((size_t)(n * 32 + c16) * HW) * 16;
    #pragma unroll
    for (int r = 0; r < 6; r++) {
        int hh = h0 - 1 + r;
        const __half* src = ((unsigned)hh < 64u) ? (xbase + (size_t)hh * 64 * 16)
                                                 : g_zero;
        BULK(sa + (r * 66 + 1) * 32, src, 2048, mb);
    }
    BULK(sa + A_BYTES, g_wB + (size_t)(c16 * 4 + cotile) * 18432, B_BYTES, mb);
}

#define LOADB(BH, addr)                                           \
    do {                                                          \
        uint32_t _bb = (addr);                                    \
        uint32_t _bq[4];                                          \
        LDSM4(_bq, _bb);          (BH)[0][0]=_bq[0]; (BH)[0][1]=_bq[1]; (BH)[1][0]=_bq[2]; (BH)[1][1]=_bq[3]; \
        LDSM4(_bq, _bb + 512);    (BH)[2][0]=_bq[0]; (BH)[2][1]=_bq[1]; (BH)[3][0]=_bq[2]; (BH)[3][1]=_bq[3]; \
        LDSM4(_bq, _bb + 1024);   (BH)[4][0]=_bq[0]; (BH)[4][1]=_bq[1]; (BH)[5][0]=_bq[2]; (BH)[5][1]=_bq[3]; \
        LDSM4(_bq, _bb + 1536);   (BH)[6][0]=_bq[0]; (BH)[6][1]=_bq[1]; (BH)[7][0]=_bq[2]; (BH)[7][1]=_bq[3]; \
    } while (0)

#define LOADA(AH, addr)                                           \
    do {                                                          \
        uint32_t _aa = (addr);                                    \
        LDSM4((AH)[0], _aa);                                      \
        LDSM4((AH)[1], _aa + 512);                                \
        LDSM4((AH)[2], _aa + 1024);                               \
        LDSM4((AH)[3], _aa + 1536);                               \
    } while (0)

// taps 0..8 -> A offset (dh*66+dw)*32
#define T0OFF (-2144)
#define TOFF_OF(tap) ((tap)==0?-2144:(tap)==1?-2112:(tap)==2?-2080:(tap)==3?-32:(tap)==4?0:(tap)==5?32:(tap)==6?2080:(tap)==7?2112:2144)

// One tap. Operands CURA/CURB already in registers. Prefetch NXTA/NXTB for tap+1
// (or next stage's tap0 when ISLAST).
#define TAPB(lsv, slotv, tapv, CURA, CURB, NXTA, NXTB, ISLAST)                   \
    do {                                                                         \
        uint32_t _saA = sb + SM_DATA + (slotv) * SSTRIDE;                        \
        if (ISLAST) { if (lane == 0) MBAR_ARRIVE(sb + 64 + (slotv) * 8); }       \
        _Pragma("unroll")                                                        \
        for (int bn = 0; bn < 8; bn++) mma_f16(acc[0][bn], (CURA)[0], CURB[bn]); \
        _Pragma("unroll")                                                        \
        for (int bn = 0; bn < 8; bn++) mma_f16(acc[1][bn], (CURA)[1], CURB[bn]); \
        if (!(ISLAST)) {                                                         \
            LOADB(NXTB, _saA + A_BYTES + ((tapv) + 1) * 4096 + boff);            \
            LOADA(NXTA, _saA + aoff0 + TOFF_OF((tapv) + 1));                     \
        } else if ((lsv) + 1 < nls) {                                            \
            uint32_t _nsa = sb + SM_DATA + (1 - (slotv)) * SSTRIDE;              \
            MBAR_WAIT(sb + (1 - (slotv)) * 8, (((lsv) + 1) >> 1) & 1);           \
            LOADB(NXTB, _nsa + A_BYTES + boff);                                  \
            LOADA(NXTA, _nsa + aoff0 + T0OFF);                                   \
        }                                                                        \
        _Pragma("unroll")                                                        \
        for (int bn = 0; bn < 8; bn++) mma_f16(acc[2][bn], (CURA)[2], CURB[bn]); \
        _Pragma("unroll")                                                        \
        for (int bn = 0; bn < 8; bn++) mma_f16(acc[3][bn], (CURA)[3], CURB[bn]); \
        if ((ISLAST) && (lsv) + 2 < nls) {                                       \
            if (wid == ((lsv) & 7) && lane == 0) {                               \
                MBAR_WAIT(sb + 64 + (slotv) * 8, ((lsv) >> 1) & 1);              \
                issue_stage(sb, (lsv) + 2, bx);                                  \
            }                                                                    \
        }                                                                        \
    } while (0)

// 9 taps; buffer parity alternates per tap, and 9 being odd alternates per stage,
// matching the caller's swapped (A0,B0)/(A1,B1) argument order.
#define STAGE(lsv, slotv, A0, B0, A1, B1)                  \
    do {                                                   \
        TAPB(lsv, slotv, 0, A0, B0, A1, B1, 0);            \
        TAPB(lsv, slotv, 1, A1, B1, A0, B0, 0);            \
        TAPB(lsv, slotv, 2, A0, B0, A1, B1, 0);            \
        TAPB(lsv, slotv, 3, A1, B1, A0, B0, 0);            \
        TAPB(lsv, slotv, 4, A0, B0, A1, B1, 0);            \
        TAPB(lsv, slotv, 5, A1, B1, A0, B0, 0);            \
        TAPB(lsv, slotv, 6, A0, B0, A1, B1, 0);            \
        TAPB(lsv, slotv, 7, A1, B1, A0, B0, 0);            \
        TAPB(lsv, slotv, 8, A0, B0, A1, B1, 1);            \
    } while (0)

__global__ void __launch_bounds__(256, 1)
k_main(const float* __restrict__ noise,
       const float* __restrict__ nw_p,
       float* __restrict__ out) {
    extern __shared__ __align__(1024) char smem[];
    uint32_t sb = smem_u32(smem);
    int t = threadIdx.x, wid = t >> 5, lane = t & 31;
    int wm = wid & 3, wn = wid >> 2;
    int bx = blockIdx.x;

    int ntiles = (NTILES_TOTAL - bx + NCTA - 1) / NCTA;
    int nls = ntiles * 32;

    if (t == 0) {
        #pragma unroll
        for (int s = 0; s < 2; s++) {
            MBAR_INIT(sb + s * 8, 1);
            MBAR_INIT(sb + 64 + s * 8, 8);
        }
    }
    {
        uint32_t zb = sb + SM_DATA;
        for (int i = t * 16; i < A_BYTES; i += 4096) {
            asm volatile(
                "st.shared.v4.b32 [%0], {%2,%2,%2,%2};\n\t"
                "st.shared.v4.b32 [%1], {%2,%2,%2,%2};"
                :: "r"(zb + i), "r"(zb + SSTRIDE + i), "r"(0u) : "memory");
        }
    }
    __syncthreads();
    if (lane == 0 && wid < 2) {
        FENCE_ASYNC();
        issue_stage(sb, wid, bx);
    }

    float acc[4][8][4];
    #pragma unroll
    for (int a = 0; a < 4; a++)
        #pragma unroll
        for (int b = 0; b < 8; b++)
            #pragma unroll
            for (int c = 0; c < 4; c++) acc[a][b][c] = 0.f;

    int bg = lane >> 3, br = lane & 7;
    uint32_t boff = (uint32_t)(wn * 64 + (bg >> 1) * 8 + br) * 32
                  + (uint32_t)(bg & 1) * 16;
    uint32_t aoff0 = (uint32_t)((wm + 1) * 66 + (lane & 15) + 1) * 32
                   + (uint32_t)(lane >> 4) * 16;

    uint32_t ahA[4][4], ahB[4][4];
    uint32_t bhA[8][2], bhB[8][2];
    float nw = nw_p[0];

    // prologue: stage 0 ready -> tap0 A+B frags
    MBAR_WAIT(sb + 0, 0);
    LOADB(bhA, sb + SM_DATA + A_BYTES + boff);
    LOADA(ahA, sb + SM_DATA + aoff0 + T0OFF);

    int tile = bx;
    for (int tord = 0; tord < ntiles; tord++, tile += NCTA) {
        int lsbase = tord * 32;
        for (int cc = 0; cc < 32; cc += 2) {
            STAGE(lsbase + cc,     0, ahA, bhA, ahB, bhB);
            STAGE(lsbase + cc + 1, 1, ahB, bhB, ahA, bhA);
        }

        // ---- warp-local epilogue (overlaps next tile's bulk loads) ----
        {
            int n   = tile >> 6;
            int rem = tile & 63;
            int p0  = (rem >> 2) * 256;
            int co0 = (rem & 3) * 128;

            int q = lane & 3, rr = lane >> 2;
            int pxbase = p0 + wm * 64 + q * 16;
            float nzs[16];
            #pragma unroll
            for (int j = 0; j < 16; j++) nzs[j] = nw * noise[n * HW + pxbase + j];

            float* wsm = reinterpret_cast<float*>(smem + SM_EPI + wid * 2048);
            const float* dmrow = g_demod + n * COUT;

            #pragma unroll
            for (int g = 0; g < 8; g++) {
                #pragma unroll
                for (int am = 0; am < 4; am++) {
                    int px = am * 16 + (lane >> 2);
                    int col = (lane & 3) * 2;
                    wsm[col * 64 + px]           = acc[am][g][0];
                    wsm[(col + 1) * 64 + px]     = acc[am][g][1];
                    wsm[col * 64 + px + 8]       = acc[am][g][2];
                    wsm[(col + 1) * 64 + px + 8] = acc[am][g][3];
                }
                __syncwarp();
                int co = co0 + wn * 64 + g * 8 + rr;
                float d = dmrow[co];
                float* op = out + ((size_t)(n * COUT + co)) * HW + pxbase;
                const float* srp = wsm + rr * 64 + q * 16;
                #pragma unroll
                for (int j4 = 0; j4 < 4; j4++) {
                    float4 v = *reinterpret_cast<const float4*>(srp + j4 * 4);
                    float r0 = v.x * d + nzs[j4 * 4 + 0];
                    float r1 = v.y * d + nzs[j4 * 4 + 1];
                    float r2 = v.z * d + nzs[j4 * 4 + 2];
                    float r3 = v.w * d + nzs[j4 * 4 + 3];
                    r0 = (r0 >= 0.f) ? r0 : 0.2f * r0;
                    r1 = (r1 >= 0.f) ? r1 : 0.2f * r1;
                    r2 = (r2 >= 0.f) ? r2 : 0.2f * r2;
                    r3 = (r3 >= 0.f) ? r3 : 0.2f * r3;
                    *reinterpret_cast<float4*>(op + j4 * 4) = make_float4(r0, r1, r2, r3);
                }
                __syncwarp();
            }
        }

        #pragma unroll
        for (int a = 0; a < 4; a++)
            #pragma unroll
            for (int b = 0; b < 8; b++)
                #pragma unroll
                for (int c = 0; c < 4; c++) acc[a][b][c] = 0.f;
    }
}

// ---------------------------------------------------------------------------
extern "C" void kernel_launch(void* const* d_in, const int* in_sizes, int n_in,
                              void* d_out, int out_size) {
    const float* x            = (const float*)d_in[0];
    const float* style        = (const float*)d_in[1];
    const float* noise        = (const float*)d_in[2];
    const float* weight       = (const float*)d_in[3];
    const float* style_w      = (const float*)d_in[4];
    const float* style_b      = (const float*)d_in[5];
    const float* noise_weight = (const float*)d_in[6];
    float* out = (float*)d_out;

    cudaFuncSetAttribute(k_main, cudaFuncAttributeMaxDynamicSharedMemorySize, SMEM_TOTAL);

    k_style<<<NB, CIN>>>(style, style_w, style_b);
    k_wprep<<<1024, 256>>>(weight);
    {
        dim3 g(COUT, NB);
        k_demod<<<g, 128>>>();
    }
    k_xmod<<<8192, 256>>>(x);
    k_main<<<NCTA, 256, SMEM_TOTAL>>>(noise, noise_weight, out);
}